// round 11
// baseline (speedup 1.0000x reference)
#include <cuda_runtime.h>
#include <cuda_fp16.h>
#include <math.h>
#include <stdint.h>

#define T_DIM 4096
#define H_DIM 1024
#define E_DIM 8
#define I_DIM 2048
#define STAGES 3

// ---------------- scratch (static device globals) ----------------
__device__ __half g_w1h[(size_t)E_DIM * 2 * I_DIM * H_DIM];   // 67 MB
__device__ __half g_w2h[(size_t)E_DIM * H_DIM * I_DIM];       // 33.5 MB
__device__ __half g_normed_h[(size_t)T_DIM * H_DIM];          // 8 MB
__device__ __half g_act_h[(size_t)E_DIM * T_DIM * I_DIM];     // 134 MB
__device__ __half g_out2h[(size_t)E_DIM * T_DIM * H_DIM];     // 67 MB
__device__ int    g_cnt[E_DIM];
__device__ int    g_tok[E_DIM * T_DIM];
__device__ int    g_slot[T_DIM * 2];
__device__ float  g_wgt[T_DIM * 2];

// ---------------- PTX helpers ----------------
__device__ __forceinline__ uint32_t smem_u32(const void* p) {
    uint32_t a;
    asm("{ .reg .u64 t; cvta.to.shared.u64 t, %1; cvt.u32.u64 %0, t; }" : "=r"(a) : "l"(p));
    return a;
}
__device__ __forceinline__ void cp16(uint32_t dst, const void* src) {
    asm volatile("cp.async.cg.shared.global [%0], [%1], 16;" :: "r"(dst), "l"(src));
}
#define CP_COMMIT() asm volatile("cp.async.commit_group;" ::: "memory")
#define CP_WAIT1()  asm volatile("cp.async.wait_group 1;" ::: "memory")
__device__ __forceinline__ void ldsm4(uint32_t* r, uint32_t addr) {
    asm volatile("ldmatrix.sync.aligned.m8n8.x4.shared.b16 {%0,%1,%2,%3}, [%4];"
        : "=r"(r[0]), "=r"(r[1]), "=r"(r[2]), "=r"(r[3]) : "r"(addr));
}
__device__ __forceinline__ void mma_f16(float* c, const uint32_t* a, const uint32_t* b) {
    asm("mma.sync.aligned.m16n8k16.row.col.f32.f16.f16.f32 "
        "{%0,%1,%2,%3},{%4,%5,%6,%7},{%8,%9},{%0,%1,%2,%3};"
        : "+f"(c[0]), "+f"(c[1]), "+f"(c[2]), "+f"(c[3])
        : "r"(a[0]), "r"(a[1]), "r"(a[2]), "r"(a[3]), "r"(b[0]), "r"(b[1]));
}
__device__ __forceinline__ float swiglu(float gv, float lv) {
    gv = fminf(gv, 7.f);
    lv = fminf(fmaxf(lv, -7.f), 7.f);
    const float sw = gv / (1.f + expf(-1.702f * gv));
    return sw * (lv + 1.f);
}

// ---------------- kernel 0: reset routing counters ----------------
__global__ void k_zero() {
    if (threadIdx.x < E_DIM) g_cnt[threadIdx.x] = 0;
}

// ---------------- kernel 1: fused RMSNorm+gate+routing (blocks 0..127)
//                            + fp32->fp16 weight convert (blocks 128..)  ----------------
#define RMS_BLOCKS 128
#define CVT_BLOCKS 4096
__global__ __launch_bounds__(256) void k_rms_cvt(
    const float* __restrict__ x, const float* __restrict__ scale,
    const float* __restrict__ gk, const float* __restrict__ gb,
    const float4* __restrict__ w1f, const float4* __restrict__ w2f)
{
    const int tid = threadIdx.x, lane = tid & 31, wid = tid >> 5;

    if (blockIdx.x >= RMS_BLOCKS) {
        // ---------------- weight conversion (grid-stride, two streams) ----------------
        const long nthr = (long)CVT_BLOCKS * 256;
        const long tg   = (long)(blockIdx.x - RMS_BLOCKS) * 256 + tid;
        const long n4_1 = (long)E_DIM * 2 * I_DIM * H_DIM / 4;
        const long n4_2 = (long)E_DIM * H_DIM * I_DIM / 4;
        uint2* d1 = (uint2*)g_w1h;
        uint2* d2 = (uint2*)g_w2h;
        for (long i = tg; i < n4_1; i += nthr) {
            const float4 v = w1f[i];
            __half2 a = __floats2half2_rn(v.x, v.y);
            __half2 b = __floats2half2_rn(v.z, v.w);
            uint2 u; u.x = *(const uint32_t*)&a; u.y = *(const uint32_t*)&b;
            d1[i] = u;
        }
        for (long i = tg; i < n4_2; i += nthr) {
            const float4 v = w2f[i];
            __half2 a = __floats2half2_rn(v.x, v.y);
            __half2 b = __floats2half2_rn(v.z, v.w);
            uint2 u; u.x = *(const uint32_t*)&a; u.y = *(const uint32_t*)&b;
            d2[i] = u;
        }
        return;
    }

    // ---------------- RMSNorm + gate + top-2 + routing (32 tokens / block) ----------------
    __shared__ float4 sgk4[2048];   // 32 KB swizzled gk
    __shared__ int    sti[64];
    __shared__ float  stw[64];

    const float4* gk4 = (const float4*)gk;
#pragma unroll
    for (int q = tid; q < 2048; q += 256)
        sgk4[q ^ ((q >> 3) & 1)] = gk4[q];
    __syncthreads();

#pragma unroll
    for (int it = 0; it < 4; it++) {
        const int t = blockIdx.x * 32 + wid * 4 + it;
        const float* xrow = x + (size_t)t * H_DIM;

        float xr[32];
        float ss = 0.f;
#pragma unroll
        for (int j = 0; j < 32; j++) {
            xr[j] = xrow[j * 32 + lane];
            ss += xr[j] * xr[j];
        }
#pragma unroll
        for (int o = 16; o > 0; o >>= 1) ss += __shfl_xor_sync(0xffffffffu, ss, o);
        const float rinv = rsqrtf(ss * (1.0f / H_DIM) + 1e-5f);

        __half* nrow = g_normed_h + (size_t)t * H_DIM;
#pragma unroll
        for (int j = 0; j < 32; j++) {
            const int h = j * 32 + lane;
            xr[j] = xr[j] * rinv * __ldg(scale + h);
            nrow[h] = __float2half_rn(xr[j]);
        }

        float acc[8];
#pragma unroll
        for (int e2 = 0; e2 < 8; e2++) acc[e2] = 0.f;
#pragma unroll
        for (int j = 0; j < 32; j++) {
            const int h = j * 32 + lane;
            const int b = (h >> 2) & 1;
            const float4 g0 = sgk4[(2 * h) ^ b];
            const float4 g1 = sgk4[(2 * h + 1) ^ b];
            const float nv = xr[j];
            acc[0] += nv * g0.x; acc[1] += nv * g0.y;
            acc[2] += nv * g0.z; acc[3] += nv * g0.w;
            acc[4] += nv * g1.x; acc[5] += nv * g1.y;
            acc[6] += nv * g1.z; acc[7] += nv * g1.w;
        }
#pragma unroll
        for (int e2 = 0; e2 < 8; e2++) {
#pragma unroll
            for (int o = 16; o > 0; o >>= 1)
                acc[e2] += __shfl_xor_sync(0xffffffffu, acc[e2], o);
        }

        if (lane == 0) {
            float lg[8];
#pragma unroll
            for (int e2 = 0; e2 < 8; e2++) lg[e2] = acc[e2] + __ldg(gb + e2);
            int i0 = 0; float l0 = lg[0];
#pragma unroll
            for (int e2 = 1; e2 < 8; e2++) { if (lg[e2] > l0) { l0 = lg[e2]; i0 = e2; } }
            int i1 = -1; float l1 = -3.4e38f;
#pragma unroll
            for (int e2 = 0; e2 < 8; e2++) {
                if (e2 != i0 && lg[e2] > l1) { l1 = lg[e2]; i1 = e2; }
            }
            const float m  = fmaxf(l0, l1);
            const float e0 = expf(l0 - m), e1f = expf(l1 - m);
            const float inv = 1.0f / (e0 + e1f);
            const int bt = wid * 4 + it;
            sti[2 * bt + 0] = i0; stw[2 * bt + 0] = e0 * inv;
            sti[2 * bt + 1] = i1; stw[2 * bt + 1] = e1f * inv;
        }
    }
    __syncthreads();

    if (tid < 8) {
        const int e = tid;
        int cnt = 0;
#pragma unroll
        for (int k = 0; k < 64; k++) cnt += (sti[k] == e) ? 1 : 0;
        int base = atomicAdd(&g_cnt[e], cnt);
        for (int k = 0; k < 64; k++) {
            if (sti[k] == e) {
                const int bt = k >> 1, ch = k & 1;
                const int t = blockIdx.x * 32 + bt;
                const int slot = e * T_DIM + base;
                g_tok[slot] = t;
                g_slot[2 * t + ch] = slot;
                g_wgt[2 * t + ch] = stw[k];
                base++;
            }
        }
    }
}

// ======================= GEMM kernels (fp16 mma + ldmatrix + cp.async) =======================
#define STAGE_BYTES 32768
#define G1_SMEM (1024 + STAGES * STAGE_BYTES)
#define G2_SMEM (1024 + STAGES * STAGE_BYTES)

// ---------------- kernel 2: grouped GEMM1 + SwiGLU -> g_act_h ----------------
__global__ __launch_bounds__(256, 2) void k_gemm1(const float* __restrict__ b1)
{
    extern __shared__ char smem[];
    const int e  = blockIdx.z;
    const int ne = g_cnt[e];
    const int m0 = blockIdx.y * 128;
    if (m0 >= ne) return;
    const int n0 = blockIdx.x * 64;
    const int tid = threadIdx.x, lane = tid & 31, wid = tid >> 5;
    const int wm = wid >> 2, wn = wid & 3;
    const uint32_t sb = smem_u32(smem);

    int* stok = (int*)smem;
    if (tid < 128) {
        const int m = m0 + tid;
        stok[tid] = g_tok[e * T_DIM + (m < ne ? m : ne - 1)];
    }
    __syncthreads();

    const __half* w1g = g_w1h + ((size_t)e * 2 * I_DIM + n0) * H_DIM;
    const __half* w1l = w1g + (size_t)I_DIM * H_DIM;

    const int c8  = tid & 7;
    const int r32 = tid >> 3;
    const uint32_t swz = (uint32_t)((c8 ^ (r32 & 7)) << 4);
    const __half* asrc[4];
    const __half* bsrc[4];
    uint32_t adst[4], bdst[4];
#pragma unroll
    for (int i = 0; i < 4; i++) {
        const int row = r32 + i * 32;
        asrc[i] = g_normed_h + (size_t)stok[row] * H_DIM + c8 * 8;
        bsrc[i] = ((row < 64) ? (w1g + (size_t)row * H_DIM)
                              : (w1l + (size_t)(row - 64) * H_DIM)) + c8 * 8;
        adst[i] = sb + 1024u + (uint32_t)row * 128u + swz;
        bdst[i] = adst[i] + 16384u;
    }

#define G1_ISSUE(kt, s) do { \
    const uint32_t so = (uint32_t)(s) * STAGE_BYTES; \
    const int ko = (kt) * 64; \
    _Pragma("unroll") \
    for (int i = 0; i < 4; i++) { \
        cp16(adst[i] + so, asrc[i] + ko); \
        cp16(bdst[i] + so, bsrc[i] + ko); \
    } } while (0)

    const int NK = H_DIM / 64;   // 16
    G1_ISSUE(0, 0); CP_COMMIT();
    G1_ISSUE(1, 1); CP_COMMIT();

    float accg[4][2][4] = {}, accl[4][2][4] = {};

    const int lr  = lane & 7;
    const int rA  = ((lane >> 3) & 1) * 8 + lr;
    const int cA  = (lane >> 4);
    const int rB  = ((lane >> 4) & 1) * 8 + lr;
    const int cB  = ((lane >> 3) & 1);

    for (int c = 0; c < NK; c++) {
        CP_WAIT1();
        __syncthreads();
        if (c + 2 < NK) G1_ISSUE(c + 2, (c + 2) % STAGES);
        CP_COMMIT();

        const uint32_t Asm = sb + 1024u + (uint32_t)(c % STAGES) * STAGE_BYTES;
        const uint32_t Bsm = Asm + 16384u;
#pragma unroll
        for (int ks = 0; ks < 4; ks++) {
            uint32_t a[4][4];
            const uint32_t chA = (uint32_t)(((2 * ks + cA) ^ lr) << 4);
#pragma unroll
            for (int mf = 0; mf < 4; mf++) {
                const int row = wm * 64 + mf * 16 + rA;
                ldsm4(a[mf], Asm + (uint32_t)row * 128u + chA);
            }
            uint32_t bg[4], bl[4];
            const uint32_t chB = (uint32_t)(((2 * ks + cB) ^ lr) << 4);
            ldsm4(bg, Bsm + (uint32_t)(wn * 16 + rB) * 128u + chB);
            ldsm4(bl, Bsm + (uint32_t)(64 + wn * 16 + rB) * 128u + chB);
#pragma unroll
            for (int mf = 0; mf < 4; mf++) {
#pragma unroll
                for (int nf = 0; nf < 2; nf++) {
                    mma_f16(accg[mf][nf], a[mf], bg + 2 * nf);
                    mma_f16(accl[mf][nf], a[mf], bl + 2 * nf);
                }
            }
        }
    }

    const float* bgb = b1 + (size_t)e * 2 * I_DIM + n0;
    const float* blb = bgb + I_DIM;
#pragma unroll
    for (int mf = 0; mf < 4; mf++) {
        const int mb = m0 + wm * 64 + mf * 16 + (lane >> 2);
#pragma unroll
        for (int h = 0; h < 2; h++) {
            const int m = mb + h * 8;
            if (m < ne) {
                __half* orow = g_act_h + ((size_t)e * T_DIM + m) * I_DIM + n0;
#pragma unroll
                for (int nf = 0; nf < 2; nf++) {
                    const int nloc = wn * 16 + nf * 8 + 2 * (lane & 3);
                    const float g0 = accg[mf][nf][2 * h + 0] + bgb[nloc];
                    const float g1 = accg[mf][nf][2 * h + 1] + bgb[nloc + 1];
                    const float l0 = accl[mf][nf][2 * h + 0] + blb[nloc];
                    const float l1 = accl[mf][nf][2 * h + 1] + blb[nloc + 1];
                    __half2 o = __floats2half2_rn(swiglu(g0, l0), swiglu(g1, l1));
                    *(__half2*)(orow + nloc) = o;
                }
            }
        }
    }
#undef G1_ISSUE
}

// ---------------- kernel 3: grouped GEMM2 + bias -> g_out2h (fp16) ----------------
__global__ __launch_bounds__(256, 2) void k_gemm2(const float* __restrict__ b2)
{
    extern __shared__ char smem[];
    const int e  = blockIdx.z;
    const int ne = g_cnt[e];
    const int m0 = blockIdx.y * 128;
    if (m0 >= ne) return;
    const int n0 = blockIdx.x * 128;
    const int tid = threadIdx.x, lane = tid & 31, wid = tid >> 5;
    const int wm = wid >> 2, wn = wid & 3;
    const uint32_t sb = smem_u32(smem);

    const __half* a_base = g_act_h + ((size_t)e * T_DIM + m0) * I_DIM;
    const __half* b_base = g_w2h + ((size_t)e * H_DIM + n0) * I_DIM;

    const int c8  = tid & 7;
    const int r32 = tid >> 3;
    const uint32_t swz = (uint32_t)((c8 ^ (r32 & 7)) << 4);
    const __half* asrc[4];
    const __half* bsrc[4];
    uint32_t adst[4], bdst[4];
#pragma unroll
    for (int i = 0; i < 4; i++) {
        const int row = r32 + i * 32;
        asrc[i] = a_base + (size_t)row * I_DIM + c8 * 8;
        bsrc[i] = b_base + (size_t)row * I_DIM + c8 * 8;
        adst[i] = sb + 1024u + (uint32_t)row * 128u + swz;
        bdst[i] = adst[i] + 16384u;
    }

#define G2_ISSUE(kt, s) do { \
    const uint32_t so = (uint32_t)(s) * STAGE_BYTES; \
    const int ko = (kt) * 64; \
    _Pragma("unroll") \
    for (int i = 0; i < 4; i++) { \
        cp16(adst[i] + so, asrc[i] + ko); \
        cp16(bdst[i] + so, bsrc[i] + ko); \
    } } while (0)

    const int NK = I_DIM / 64;   // 32
    G2_ISSUE(0, 0); CP_COMMIT();
    G2_ISSUE(1, 1); CP_COMMIT();

    float acc[4][4][4] = {};

    const int lr  = lane & 7;
    const int rA  = ((lane >> 3) & 1) * 8 + lr;
    const int cA  = (lane >> 4);
    const int rB  = ((lane >> 4) & 1) * 8 + lr;
    const int cB  = ((lane >> 3) & 1);

    for (int c = 0; c < NK; c++) {
        CP_WAIT1();
        __syncthreads();
        if (c + 2 < NK) G2_ISSUE(c + 2, (c + 2) % STAGES);
        CP_COMMIT();

        const uint32_t Asm = sb + 1024u + (uint32_t)(c % STAGES) * STAGE_BYTES;
        const uint32_t Bsm = Asm + 16384u;
#pragma unroll
        for (int ks = 0; ks < 4; ks++) {
            uint32_t a[4][4];
            const uint32_t chA = (uint32_t)(((2 * ks + cA) ^ lr) << 4);
#pragma unroll
            for (int mf = 0; mf < 4; mf++) {
                const int row = wm * 64 + mf * 16 + rA;
                ldsm4(a[mf], Asm + (uint32_t)row * 128u + chA);
            }
            uint32_t b[2][4];
            const uint32_t chB = (uint32_t)(((2 * ks + cB) ^ lr) << 4);
            ldsm4(b[0], Bsm + (uint32_t)(wn * 32 + rB) * 128u + chB);
            ldsm4(b[1], Bsm + (uint32_t)(wn * 32 + 16 + rB) * 128u + chB);
#pragma unroll
            for (int mf = 0; mf < 4; mf++) {
#pragma unroll
                for (int nf = 0; nf < 4; nf++)
                    mma_f16(acc[mf][nf], a[mf], b[nf >> 1] + 2 * (nf & 1));
            }
        }
    }

    const float* bb = b2 + (size_t)e * H_DIM + n0;
#pragma unroll
    for (int mf = 0; mf < 4; mf++) {
        const int mb = m0 + wm * 64 + mf * 16 + (lane >> 2);
#pragma unroll
        for (int h = 0; h < 2; h++) {
            const int m = mb + h * 8;
            if (m < ne) {
                __half* orow = g_out2h + ((size_t)e * T_DIM + m) * H_DIM + n0;
#pragma unroll
                for (int nf = 0; nf < 4; nf++) {
                    const int nloc = wn * 32 + nf * 8 + 2 * (lane & 3);
                    __half2 o = __floats2half2_rn(acc[mf][nf][2 * h + 0] + bb[nloc],
                                                  acc[mf][nf][2 * h + 1] + bb[nloc + 1]);
                    *(__half2*)(orow + nloc) = o;
                }
            }
        }
    }
#undef G2_ISSUE
}

// ---------------- kernel 4: gather-combine + residual ----------------
__global__ __launch_bounds__(256) void k_combine(
    const float* __restrict__ x, float* __restrict__ out)
{
    const size_t idx = (size_t)blockIdx.x * blockDim.x + threadIdx.x;  // over T*H/8
    if (idx >= (size_t)T_DIM * H_DIM / 8) return;
    const int t  = (int)(idx / (H_DIM / 8));
    const int hc = (int)(idx % (H_DIM / 8)) * 8;

    const int   s0 = g_slot[2 * t + 0], s1 = g_slot[2 * t + 1];
    const float w0 = g_wgt[2 * t + 0],  w1 = g_wgt[2 * t + 1];

    const __half2* o0p = (const __half2*)(g_out2h + (size_t)s0 * H_DIM + hc);
    const __half2* o1p = (const __half2*)(g_out2h + (size_t)s1 * H_DIM + hc);
    const float4 u0 = *(const float4*)o0p;   // 8 halves
    const float4 u1 = *(const float4*)o1p;
    const __half2* h0 = (const __half2*)&u0;
    const __half2* h1 = (const __half2*)&u1;

    const float* xp = x + (size_t)t * H_DIM + hc;
    float* op = out + (size_t)t * H_DIM + hc;
    const float4 xa = *(const float4*)xp;
    const float4 xb = *(const float4*)(xp + 4);

    float r[8];
#pragma unroll
    for (int q = 0; q < 4; q++) {
        const float2 f0 = __half22float2(h0[q]);
        const float2 f1 = __half22float2(h1[q]);
        r[2 * q + 0] = w0 * f0.x + w1 * f1.x;
        r[2 * q + 1] = w0 * f0.y + w1 * f1.y;
    }
    float4 oa = { xa.x + r[0], xa.y + r[1], xa.z + r[2], xa.w + r[3] };
    float4 ob = { xb.x + r[4], xb.y + r[5], xb.z + r[6], xb.w + r[7] };
    *(float4*)op = oa;
    *(float4*)(op + 4) = ob;
}

// ---------------- launch ----------------
extern "C" void kernel_launch(void* const* d_in, const int* in_sizes, int n_in,
                              void* d_out, int out_size)
{
    const float* x     = (const float*)d_in[0];
    const float* scale = (const float*)d_in[1];
    const float* gk    = (const float*)d_in[2];
    const float* gb    = (const float*)d_in[3];
    const float* w1    = (const float*)d_in[4];
    const float* b1    = (const float*)d_in[5];
    const float* w2    = (const float*)d_in[6];
    const float* b2    = (const float*)d_in[7];
    float* out = (float*)d_out;

    cudaFuncSetAttribute(k_gemm1, cudaFuncAttributeMaxDynamicSharedMemorySize, G1_SMEM);
    cudaFuncSetAttribute(k_gemm2, cudaFuncAttributeMaxDynamicSharedMemorySize, G2_SMEM);

    k_zero<<<1, 32>>>();

    k_rms_cvt<<<RMS_BLOCKS + CVT_BLOCKS, 256>>>(x, scale, gk, gb,
                                                (const float4*)w1, (const float4*)w2);

    dim3 g1(I_DIM / 64, T_DIM / 128, E_DIM);    // 32 x 32 x 8
    k_gemm1<<<g1, 256, G1_SMEM>>>(b1);

    dim3 g2(H_DIM / 128, T_DIM / 128, E_DIM);   // 8 x 32 x 8
    k_gemm2<<<g2, 256, G2_SMEM>>>(b2);

    k_combine<<<(T_DIM * H_DIM / 8 + 255) / 256, 256>>>(x, out);
}

// round 12
// speedup vs baseline: 1.0623x; 1.0623x over previous
#include <cuda_runtime.h>
#include <cuda_fp16.h>
#include <math.h>
#include <stdint.h>

#define T_DIM 4096
#define H_DIM 1024
#define E_DIM 8
#define I_DIM 2048
#define STAGES 3

// ---------------- scratch (static device globals) ----------------
__device__ __half g_w1h[(size_t)E_DIM * 2 * I_DIM * H_DIM];   // 67 MB
__device__ __half g_w2h[(size_t)E_DIM * H_DIM * I_DIM];       // 33.5 MB
__device__ __half g_normed_h[(size_t)T_DIM * H_DIM];          // 8 MB
__device__ __half g_act_h[(size_t)E_DIM * T_DIM * I_DIM];     // 134 MB
__device__ __half g_out2h[(size_t)E_DIM * T_DIM * H_DIM];     // 67 MB
__device__ int    g_cnt[E_DIM];
__device__ int    g_tok[E_DIM * T_DIM];
__device__ int    g_slot[T_DIM * 2];
__device__ float  g_wgt[T_DIM * 2];

// ---------------- PTX helpers ----------------
__device__ __forceinline__ uint32_t smem_u32(const void* p) {
    uint32_t a;
    asm("{ .reg .u64 t; cvta.to.shared.u64 t, %1; cvt.u32.u64 %0, t; }" : "=r"(a) : "l"(p));
    return a;
}
__device__ __forceinline__ void cp16(uint32_t dst, const void* src) {
    asm volatile("cp.async.cg.shared.global [%0], [%1], 16;" :: "r"(dst), "l"(src));
}
#define CP_COMMIT() asm volatile("cp.async.commit_group;" ::: "memory")
#define CP_WAIT1()  asm volatile("cp.async.wait_group 1;" ::: "memory")
__device__ __forceinline__ void ldsm4(uint32_t* r, uint32_t addr) {
    asm volatile("ldmatrix.sync.aligned.m8n8.x4.shared.b16 {%0,%1,%2,%3}, [%4];"
        : "=r"(r[0]), "=r"(r[1]), "=r"(r[2]), "=r"(r[3]) : "r"(addr));
}
__device__ __forceinline__ void mma_f16(float* c, const uint32_t* a, const uint32_t* b) {
    asm("mma.sync.aligned.m16n8k16.row.col.f32.f16.f16.f32 "
        "{%0,%1,%2,%3},{%4,%5,%6,%7},{%8,%9},{%0,%1,%2,%3};"
        : "+f"(c[0]), "+f"(c[1]), "+f"(c[2]), "+f"(c[3])
        : "r"(a[0]), "r"(a[1]), "r"(a[2]), "r"(a[3]), "r"(b[0]), "r"(b[1]));
}
__device__ __forceinline__ float swiglu(float gv, float lv) {
    gv = fminf(gv, 7.f);
    lv = fminf(fmaxf(lv, -7.f), 7.f);
    const float sw = gv / (1.f + expf(-1.702f * gv));
    return sw * (lv + 1.f);
}

// ---------------- kernel: fp32 -> fp16 conversion (full-occupancy streaming) ----------------
__global__ __launch_bounds__(256) void k_cvt(const float4* __restrict__ src,
                                             uint2* __restrict__ dst, int n4)
{
    const int i = blockIdx.x * 256 + threadIdx.x;
    if (i < n4) {
        const float4 v = src[i];
        __half2 a = __floats2half2_rn(v.x, v.y);
        __half2 b = __floats2half2_rn(v.z, v.w);
        uint2 u;
        u.x = *(const uint32_t*)&a;
        u.y = *(const uint32_t*)&b;
        dst[i] = u;
    }
}

// ---------------- kernel 0: reset routing counters ----------------
__global__ void k_zero() {
    if (threadIdx.x < E_DIM) g_cnt[threadIdx.x] = 0;
}

// ---------------- kernel 1: RMSNorm + gate + top-2 + routing ----------------
// 16 tokens per block (256 blocks); warp w handles tokens base + 2w, 2w+1.
// gk staged once per block in SMEM (swizzled); routing atomics aggregated: 8/block.
__global__ __launch_bounds__(256) void k_rms_gate(
    const float* __restrict__ x, const float* __restrict__ scale,
    const float* __restrict__ gk, const float* __restrict__ gb)
{
    __shared__ float4 sgk4[2048];   // 32 KB swizzled gk
    __shared__ int    sti[32];
    __shared__ float  stw[32];

    const int tid = threadIdx.x, lane = tid & 31, wid = tid >> 5;

    const float4* gk4 = (const float4*)gk;
#pragma unroll
    for (int q = tid; q < 2048; q += 256)
        sgk4[q ^ ((q >> 3) & 1)] = gk4[q];
    __syncthreads();

#pragma unroll
    for (int it = 0; it < 2; it++) {
        const int t = blockIdx.x * 16 + wid * 2 + it;
        const float* xrow = x + (size_t)t * H_DIM;

        float xr[32];
        float ss = 0.f;
#pragma unroll
        for (int j = 0; j < 32; j++) {
            xr[j] = xrow[j * 32 + lane];
            ss += xr[j] * xr[j];
        }
#pragma unroll
        for (int o = 16; o > 0; o >>= 1) ss += __shfl_xor_sync(0xffffffffu, ss, o);
        const float rinv = rsqrtf(ss * (1.0f / H_DIM) + 1e-5f);

        __half* nrow = g_normed_h + (size_t)t * H_DIM;
#pragma unroll
        for (int j = 0; j < 32; j++) {
            const int h = j * 32 + lane;
            xr[j] = xr[j] * rinv * __ldg(scale + h);
            nrow[h] = __float2half_rn(xr[j]);
        }

        float acc[8];
#pragma unroll
        for (int e2 = 0; e2 < 8; e2++) acc[e2] = 0.f;
#pragma unroll
        for (int j = 0; j < 32; j++) {
            const int h = j * 32 + lane;
            const int b = (h >> 2) & 1;
            const float4 g0 = sgk4[(2 * h) ^ b];
            const float4 g1 = sgk4[(2 * h + 1) ^ b];
            const float nv = xr[j];
            acc[0] += nv * g0.x; acc[1] += nv * g0.y;
            acc[2] += nv * g0.z; acc[3] += nv * g0.w;
            acc[4] += nv * g1.x; acc[5] += nv * g1.y;
            acc[6] += nv * g1.z; acc[7] += nv * g1.w;
        }
#pragma unroll
        for (int e2 = 0; e2 < 8; e2++) {
#pragma unroll
            for (int o = 16; o > 0; o >>= 1)
                acc[e2] += __shfl_xor_sync(0xffffffffu, acc[e2], o);
        }

        if (lane == 0) {
            float lg[8];
#pragma unroll
            for (int e2 = 0; e2 < 8; e2++) lg[e2] = acc[e2] + __ldg(gb + e2);
            int i0 = 0; float l0 = lg[0];
#pragma unroll
            for (int e2 = 1; e2 < 8; e2++) { if (lg[e2] > l0) { l0 = lg[e2]; i0 = e2; } }
            int i1 = -1; float l1 = -3.4e38f;
#pragma unroll
            for (int e2 = 0; e2 < 8; e2++) {
                if (e2 != i0 && lg[e2] > l1) { l1 = lg[e2]; i1 = e2; }
            }
            const float m  = fmaxf(l0, l1);
            const float e0 = expf(l0 - m), e1f = expf(l1 - m);
            const float inv = 1.0f / (e0 + e1f);
            const int bt = wid * 2 + it;
            sti[2 * bt + 0] = i0; stw[2 * bt + 0] = e0 * inv;
            sti[2 * bt + 1] = i1; stw[2 * bt + 1] = e1f * inv;
        }
    }
    __syncthreads();

    if (tid < 8) {
        const int e = tid;
        int cnt = 0;
#pragma unroll
        for (int k = 0; k < 32; k++) cnt += (sti[k] == e) ? 1 : 0;
        int base = atomicAdd(&g_cnt[e], cnt);
        for (int k = 0; k < 32; k++) {
            if (sti[k] == e) {
                const int bt = k >> 1, ch = k & 1;
                const int t = blockIdx.x * 16 + bt;
                const int slot = e * T_DIM + base;
                g_tok[slot] = t;
                g_slot[2 * t + ch] = slot;
                g_wgt[2 * t + ch] = stw[k];
                base++;
            }
        }
    }
}

// ======================= GEMM kernels (fp16 mma + ldmatrix + cp.async) =======================
#define STAGE_BYTES 32768
#define G1_SMEM (1024 + STAGES * STAGE_BYTES)
#define G2_SMEM (1024 + STAGES * STAGE_BYTES)

// ---------------- kernel 2: grouped GEMM1 + SwiGLU -> g_act_h ----------------
__global__ __launch_bounds__(256, 2) void k_gemm1(const float* __restrict__ b1)
{
    extern __shared__ char smem[];
    const int e  = blockIdx.z;
    const int ne = g_cnt[e];
    const int m0 = blockIdx.y * 128;
    if (m0 >= ne) return;
    const int n0 = blockIdx.x * 64;
    const int tid = threadIdx.x, lane = tid & 31, wid = tid >> 5;
    const int wm = wid >> 2, wn = wid & 3;
    const uint32_t sb = smem_u32(smem);

    int* stok = (int*)smem;
    if (tid < 128) {
        const int m = m0 + tid;
        stok[tid] = g_tok[e * T_DIM + (m < ne ? m : ne - 1)];
    }
    __syncthreads();

    const __half* w1g = g_w1h + ((size_t)e * 2 * I_DIM + n0) * H_DIM;
    const __half* w1l = w1g + (size_t)I_DIM * H_DIM;

    const int c8  = tid & 7;
    const int r32 = tid >> 3;
    const uint32_t swz = (uint32_t)((c8 ^ (r32 & 7)) << 4);
    const __half* asrc[4];
    const __half* bsrc[4];
    uint32_t adst[4], bdst[4];
#pragma unroll
    for (int i = 0; i < 4; i++) {
        const int row = r32 + i * 32;
        asrc[i] = g_normed_h + (size_t)stok[row] * H_DIM + c8 * 8;
        bsrc[i] = ((row < 64) ? (w1g + (size_t)row * H_DIM)
                              : (w1l + (size_t)(row - 64) * H_DIM)) + c8 * 8;
        adst[i] = sb + 1024u + (uint32_t)row * 128u + swz;
        bdst[i] = adst[i] + 16384u;
    }

#define G1_ISSUE(kt, s) do { \
    const uint32_t so = (uint32_t)(s) * STAGE_BYTES; \
    const int ko = (kt) * 64; \
    _Pragma("unroll") \
    for (int i = 0; i < 4; i++) { \
        cp16(adst[i] + so, asrc[i] + ko); \
        cp16(bdst[i] + so, bsrc[i] + ko); \
    } } while (0)

    const int NK = H_DIM / 64;   // 16
    G1_ISSUE(0, 0); CP_COMMIT();
    G1_ISSUE(1, 1); CP_COMMIT();

    float accg[4][2][4] = {}, accl[4][2][4] = {};

    const int lr  = lane & 7;
    const int rA  = ((lane >> 3) & 1) * 8 + lr;
    const int cA  = (lane >> 4);
    const int rB  = ((lane >> 4) & 1) * 8 + lr;
    const int cB  = ((lane >> 3) & 1);

    for (int c = 0; c < NK; c++) {
        CP_WAIT1();
        __syncthreads();
        if (c + 2 < NK) G1_ISSUE(c + 2, (c + 2) % STAGES);
        CP_COMMIT();

        const uint32_t Asm = sb + 1024u + (uint32_t)(c % STAGES) * STAGE_BYTES;
        const uint32_t Bsm = Asm + 16384u;
#pragma unroll
        for (int ks = 0; ks < 4; ks++) {
            uint32_t a[4][4];
            const uint32_t chA = (uint32_t)(((2 * ks + cA) ^ lr) << 4);
#pragma unroll
            for (int mf = 0; mf < 4; mf++) {
                const int row = wm * 64 + mf * 16 + rA;
                ldsm4(a[mf], Asm + (uint32_t)row * 128u + chA);
            }
            uint32_t bg[4], bl[4];
            const uint32_t chB = (uint32_t)(((2 * ks + cB) ^ lr) << 4);
            ldsm4(bg, Bsm + (uint32_t)(wn * 16 + rB) * 128u + chB);
            ldsm4(bl, Bsm + (uint32_t)(64 + wn * 16 + rB) * 128u + chB);
#pragma unroll
            for (int mf = 0; mf < 4; mf++) {
#pragma unroll
                for (int nf = 0; nf < 2; nf++) {
                    mma_f16(accg[mf][nf], a[mf], bg + 2 * nf);
                    mma_f16(accl[mf][nf], a[mf], bl + 2 * nf);
                }
            }
        }
    }

    const float* bgb = b1 + (size_t)e * 2 * I_DIM + n0;
    const float* blb = bgb + I_DIM;
#pragma unroll
    for (int mf = 0; mf < 4; mf++) {
        const int mb = m0 + wm * 64 + mf * 16 + (lane >> 2);
#pragma unroll
        for (int h = 0; h < 2; h++) {
            const int m = mb + h * 8;
            if (m < ne) {
                __half* orow = g_act_h + ((size_t)e * T_DIM + m) * I_DIM + n0;
#pragma unroll
                for (int nf = 0; nf < 2; nf++) {
                    const int nloc = wn * 16 + nf * 8 + 2 * (lane & 3);
                    const float g0 = accg[mf][nf][2 * h + 0] + bgb[nloc];
                    const float g1 = accg[mf][nf][2 * h + 1] + bgb[nloc + 1];
                    const float l0 = accl[mf][nf][2 * h + 0] + blb[nloc];
                    const float l1 = accl[mf][nf][2 * h + 1] + blb[nloc + 1];
                    __half2 o = __floats2half2_rn(swiglu(g0, l0), swiglu(g1, l1));
                    *(__half2*)(orow + nloc) = o;
                }
            }
        }
    }
#undef G1_ISSUE
}

// ---------------- kernel 3: grouped GEMM2 + bias -> g_out2h (fp16) ----------------
__global__ __launch_bounds__(256, 2) void k_gemm2(const float* __restrict__ b2)
{
    extern __shared__ char smem[];
    const int e  = blockIdx.z;
    const int ne = g_cnt[e];
    const int m0 = blockIdx.y * 128;
    if (m0 >= ne) return;
    const int n0 = blockIdx.x * 128;
    const int tid = threadIdx.x, lane = tid & 31, wid = tid >> 5;
    const int wm = wid >> 2, wn = wid & 3;
    const uint32_t sb = smem_u32(smem);

    const __half* a_base = g_act_h + ((size_t)e * T_DIM + m0) * I_DIM;
    const __half* b_base = g_w2h + ((size_t)e * H_DIM + n0) * I_DIM;

    const int c8  = tid & 7;
    const int r32 = tid >> 3;
    const uint32_t swz = (uint32_t)((c8 ^ (r32 & 7)) << 4);
    const __half* asrc[4];
    const __half* bsrc[4];
    uint32_t adst[4], bdst[4];
#pragma unroll
    for (int i = 0; i < 4; i++) {
        const int row = r32 + i * 32;
        asrc[i] = a_base + (size_t)row * I_DIM + c8 * 8;
        bsrc[i] = b_base + (size_t)row * I_DIM + c8 * 8;
        adst[i] = sb + 1024u + (uint32_t)row * 128u + swz;
        bdst[i] = adst[i] + 16384u;
    }

#define G2_ISSUE(kt, s) do { \
    const uint32_t so = (uint32_t)(s) * STAGE_BYTES; \
    const int ko = (kt) * 64; \
    _Pragma("unroll") \
    for (int i = 0; i < 4; i++) { \
        cp16(adst[i] + so, asrc[i] + ko); \
        cp16(bdst[i] + so, bsrc[i] + ko); \
    } } while (0)

    const int NK = I_DIM / 64;   // 32
    G2_ISSUE(0, 0); CP_COMMIT();
    G2_ISSUE(1, 1); CP_COMMIT();

    float acc[4][4][4] = {};

    const int lr  = lane & 7;
    const int rA  = ((lane >> 3) & 1) * 8 + lr;
    const int cA  = (lane >> 4);
    const int rB  = ((lane >> 4) & 1) * 8 + lr;
    const int cB  = ((lane >> 3) & 1);

    for (int c = 0; c < NK; c++) {
        CP_WAIT1();
        __syncthreads();
        if (c + 2 < NK) G2_ISSUE(c + 2, (c + 2) % STAGES);
        CP_COMMIT();

        const uint32_t Asm = sb + 1024u + (uint32_t)(c % STAGES) * STAGE_BYTES;
        const uint32_t Bsm = Asm + 16384u;
#pragma unroll
        for (int ks = 0; ks < 4; ks++) {
            uint32_t a[4][4];
            const uint32_t chA = (uint32_t)(((2 * ks + cA) ^ lr) << 4);
#pragma unroll
            for (int mf = 0; mf < 4; mf++) {
                const int row = wm * 64 + mf * 16 + rA;
                ldsm4(a[mf], Asm + (uint32_t)row * 128u + chA);
            }
            uint32_t b[2][4];
            const uint32_t chB = (uint32_t)(((2 * ks + cB) ^ lr) << 4);
            ldsm4(b[0], Bsm + (uint32_t)(wn * 32 + rB) * 128u + chB);
            ldsm4(b[1], Bsm + (uint32_t)(wn * 32 + 16 + rB) * 128u + chB);
#pragma unroll
            for (int mf = 0; mf < 4; mf++) {
#pragma unroll
                for (int nf = 0; nf < 4; nf++)
                    mma_f16(acc[mf][nf], a[mf], b[nf >> 1] + 2 * (nf & 1));
            }
        }
    }

    const float* bb = b2 + (size_t)e * H_DIM + n0;
#pragma unroll
    for (int mf = 0; mf < 4; mf++) {
        const int mb = m0 + wm * 64 + mf * 16 + (lane >> 2);
#pragma unroll
        for (int h = 0; h < 2; h++) {
            const int m = mb + h * 8;
            if (m < ne) {
                __half* orow = g_out2h + ((size_t)e * T_DIM + m) * H_DIM + n0;
#pragma unroll
                for (int nf = 0; nf < 4; nf++) {
                    const int nloc = wn * 32 + nf * 8 + 2 * (lane & 3);
                    __half2 o = __floats2half2_rn(acc[mf][nf][2 * h + 0] + bb[nloc],
                                                  acc[mf][nf][2 * h + 1] + bb[nloc + 1]);
                    *(__half2*)(orow + nloc) = o;
                }
            }
        }
    }
#undef G2_ISSUE
}

// ---------------- kernel 4: gather-combine + residual (8 elems / thread) ----------------
__global__ __launch_bounds__(256) void k_combine(
    const float* __restrict__ x, float* __restrict__ out)
{
    const size_t idx = (size_t)blockIdx.x * blockDim.x + threadIdx.x;  // over T*H/8
    if (idx >= (size_t)T_DIM * H_DIM / 8) return;
    const int t  = (int)(idx / (H_DIM / 8));
    const int hc = (int)(idx % (H_DIM / 8)) * 8;

    const int   s0 = g_slot[2 * t + 0], s1 = g_slot[2 * t + 1];
    const float w0 = g_wgt[2 * t + 0],  w1 = g_wgt[2 * t + 1];

    const float4 u0 = *(const float4*)(g_out2h + (size_t)s0 * H_DIM + hc);   // 8 halves
    const float4 u1 = *(const float4*)(g_out2h + (size_t)s1 * H_DIM + hc);
    const __half2* h0 = (const __half2*)&u0;
    const __half2* h1 = (const __half2*)&u1;

    const float* xp = x + (size_t)t * H_DIM + hc;
    float* op = out + (size_t)t * H_DIM + hc;
    const float4 xa = *(const float4*)xp;
    const float4 xb = *(const float4*)(xp + 4);

    float r[8];
#pragma unroll
    for (int q = 0; q < 4; q++) {
        const float2 f0 = __half22float2(h0[q]);
        const float2 f1 = __half22float2(h1[q]);
        r[2 * q + 0] = w0 * f0.x + w1 * f1.x;
        r[2 * q + 1] = w0 * f0.y + w1 * f1.y;
    }
    float4 oa = { xa.x + r[0], xa.y + r[1], xa.z + r[2], xa.w + r[3] };
    float4 ob = { xb.x + r[4], xb.y + r[5], xb.z + r[6], xb.w + r[7] };
    *(float4*)op = oa;
    *(float4*)(op + 4) = ob;
}

// ---------------- launch ----------------
extern "C" void kernel_launch(void* const* d_in, const int* in_sizes, int n_in,
                              void* d_out, int out_size)
{
    const float* x     = (const float*)d_in[0];
    const float* scale = (const float*)d_in[1];
    const float* gk    = (const float*)d_in[2];
    const float* gb    = (const float*)d_in[3];
    const float* w1    = (const float*)d_in[4];
    const float* b1    = (const float*)d_in[5];
    const float* w2    = (const float*)d_in[6];
    const float* b2    = (const float*)d_in[7];
    float* out = (float*)d_out;

    cudaFuncSetAttribute(k_gemm1, cudaFuncAttributeMaxDynamicSharedMemorySize, G1_SMEM);
    cudaFuncSetAttribute(k_gemm2, cudaFuncAttributeMaxDynamicSharedMemorySize, G2_SMEM);

    k_zero<<<1, 32>>>();

    {
        __half* w1h_p; cudaGetSymbolAddress((void**)&w1h_p, g_w1h);
        __half* w2h_p; cudaGetSymbolAddress((void**)&w2h_p, g_w2h);
        const int n4_1 = E_DIM * 2 * I_DIM * H_DIM / 4;
        const int n4_2 = E_DIM * H_DIM * I_DIM / 4;
        k_cvt<<<n4_1 / 256, 256>>>((const float4*)w1, (uint2*)w1h_p, n4_1);
        k_cvt<<<n4_2 / 256, 256>>>((const float4*)w2, (uint2*)w2h_p, n4_2);
    }

    k_rms_gate<<<T_DIM / 16, 256>>>(x, scale, gk, gb);

    dim3 g1(I_DIM / 64, T_DIM / 128, E_DIM);    // 32 x 32 x 8
    k_gemm1<<<g1, 256, G1_SMEM>>>(b1);

    dim3 g2(H_DIM / 128, T_DIM / 128, E_DIM);   // 8 x 32 x 8
    k_gemm2<<<g2, 256, G2_SMEM>>>(b2);

    k_combine<<<(T_DIM * H_DIM / 8 + 255) / 256, 256>>>(x, out);
}

// round 14
// speedup vs baseline: 1.0883x; 1.0245x over previous
#include <cuda_runtime.h>
#include <cuda_fp16.h>
#include <math.h>
#include <stdint.h>

#define T_DIM 4096
#define H_DIM 1024
#define E_DIM 8
#define I_DIM 2048
#define STAGES 3

// ---------------- scratch (static device globals) ----------------
__device__ __half g_w1h[(size_t)E_DIM * 2 * I_DIM * H_DIM];   // 67 MB
__device__ __half g_w2h[(size_t)E_DIM * H_DIM * I_DIM];       // 33.5 MB
__device__ __half g_normed_h[(size_t)T_DIM * H_DIM];          // 8 MB
__device__ __half g_act_h[(size_t)E_DIM * T_DIM * I_DIM];     // 134 MB
__device__ __half g_out2h[(size_t)E_DIM * T_DIM * H_DIM];     // 67 MB
__device__ int    g_cnt[E_DIM];
__device__ int    g_tok[E_DIM * T_DIM];
__device__ int    g_slot[T_DIM * 2];
__device__ float  g_wgt[T_DIM * 2];

// ---------------- PTX helpers ----------------
__device__ __forceinline__ uint32_t smem_u32(const void* p) {
    uint32_t a;
    asm("{ .reg .u64 t; cvta.to.shared.u64 t, %1; cvt.u32.u64 %0, t; }" : "=r"(a) : "l"(p));
    return a;
}
__device__ __forceinline__ void cp16(uint32_t dst, const void* src) {
    asm volatile("cp.async.cg.shared.global [%0], [%1], 16;" :: "r"(dst), "l"(src));
}
#define CP_COMMIT() asm volatile("cp.async.commit_group;" ::: "memory")
#define CP_WAIT1()  asm volatile("cp.async.wait_group 1;" ::: "memory")
__device__ __forceinline__ void ldsm4(uint32_t* r, uint32_t addr) {
    asm volatile("ldmatrix.sync.aligned.m8n8.x4.shared.b16 {%0,%1,%2,%3}, [%4];"
        : "=r"(r[0]), "=r"(r[1]), "=r"(r[2]), "=r"(r[3]) : "r"(addr));
}
__device__ __forceinline__ void mma_f16(float* c, const uint32_t* a, const uint32_t* b) {
    asm("mma.sync.aligned.m16n8k16.row.col.f32.f16.f16.f32 "
        "{%0,%1,%2,%3},{%4,%5,%6,%7},{%8,%9},{%0,%1,%2,%3};"
        : "+f"(c[0]), "+f"(c[1]), "+f"(c[2]), "+f"(c[3])
        : "r"(a[0]), "r"(a[1]), "r"(a[2]), "r"(a[3]), "r"(b[0]), "r"(b[1]));
}
__device__ __forceinline__ uint2 cvt4(float4 v) {
    __half2 a = __floats2half2_rn(v.x, v.y);
    __half2 b = __floats2half2_rn(v.z, v.w);
    uint2 u;
    u.x = *(const uint32_t*)&a;
    u.y = *(const uint32_t*)&b;
    return u;
}
__device__ __forceinline__ float swiglu(float gv, float lv) {
    gv = fminf(gv, 7.f);
    lv = fminf(fmaxf(lv, -7.f), 7.f);
    const float sw = gv / (1.f + expf(-1.702f * gv));
    return sw * (lv + 1.f);
}

// ---------------- kernel: w1 fp32 -> fp16 conversion + counter zero ----------------
__global__ __launch_bounds__(256) void k_cvt(const float4* __restrict__ src,
                                             uint2* __restrict__ dst, int n4)
{
    const int i = blockIdx.x * 256 + threadIdx.x;
    if (blockIdx.x == 0 && threadIdx.x < E_DIM) g_cnt[threadIdx.x] = 0;
    if (i < n4) dst[i] = cvt4(src[i]);
}

// ---------------- kernel 1: RMSNorm + gate + top-2 + routing ----------------
// 16 tokens per block (256 blocks); warp w handles tokens base + 2w, 2w+1.
__global__ __launch_bounds__(256) void k_rms_gate(
    const float* __restrict__ x, const float* __restrict__ scale,
    const float* __restrict__ gk, const float* __restrict__ gb)
{
    __shared__ float4 sgk4[2048];   // 32 KB swizzled gk
    __shared__ int    sti[32];
    __shared__ float  stw[32];

    const int tid = threadIdx.x, lane = tid & 31, wid = tid >> 5;

    const float4* gk4 = (const float4*)gk;
#pragma unroll
    for (int q = tid; q < 2048; q += 256)
        sgk4[q ^ ((q >> 3) & 1)] = gk4[q];
    __syncthreads();

#pragma unroll
    for (int it = 0; it < 2; it++) {
        const int t = blockIdx.x * 16 + wid * 2 + it;
        const float* xrow = x + (size_t)t * H_DIM;

        float xr[32];
        float ss = 0.f;
#pragma unroll
        for (int j = 0; j < 32; j++) {
            xr[j] = xrow[j * 32 + lane];
            ss += xr[j] * xr[j];
        }
#pragma unroll
        for (int o = 16; o > 0; o >>= 1) ss += __shfl_xor_sync(0xffffffffu, ss, o);
        const float rinv = rsqrtf(ss * (1.0f / H_DIM) + 1e-5f);

        __half* nrow = g_normed_h + (size_t)t * H_DIM;
#pragma unroll
        for (int j = 0; j < 32; j++) {
            const int h = j * 32 + lane;
            xr[j] = xr[j] * rinv * __ldg(scale + h);
            nrow[h] = __float2half_rn(xr[j]);
        }

        float acc[8];
#pragma unroll
        for (int e2 = 0; e2 < 8; e2++) acc[e2] = 0.f;
#pragma unroll
        for (int j = 0; j < 32; j++) {
            const int h = j * 32 + lane;
            const int b = (h >> 2) & 1;
            const float4 g0 = sgk4[(2 * h) ^ b];
            const float4 g1 = sgk4[(2 * h + 1) ^ b];
            const float nv = xr[j];
            acc[0] += nv * g0.x; acc[1] += nv * g0.y;
            acc[2] += nv * g0.z; acc[3] += nv * g0.w;
            acc[4] += nv * g1.x; acc[5] += nv * g1.y;
            acc[6] += nv * g1.z; acc[7] += nv * g1.w;
        }
#pragma unroll
        for (int e2 = 0; e2 < 8; e2++) {
#pragma unroll
            for (int o = 16; o > 0; o >>= 1)
                acc[e2] += __shfl_xor_sync(0xffffffffu, acc[e2], o);
        }

        if (lane == 0) {
            float lg[8];
#pragma unroll
            for (int e2 = 0; e2 < 8; e2++) lg[e2] = acc[e2] + __ldg(gb + e2);
            int i0 = 0; float l0 = lg[0];
#pragma unroll
            for (int e2 = 1; e2 < 8; e2++) { if (lg[e2] > l0) { l0 = lg[e2]; i0 = e2; } }
            int i1 = -1; float l1 = -3.4e38f;
#pragma unroll
            for (int e2 = 0; e2 < 8; e2++) {
                if (e2 != i0 && lg[e2] > l1) { l1 = lg[e2]; i1 = e2; }
            }
            const float m  = fmaxf(l0, l1);
            const float e0 = expf(l0 - m), e1f = expf(l1 - m);
            const float inv = 1.0f / (e0 + e1f);
            const int bt = wid * 2 + it;
            sti[2 * bt + 0] = i0; stw[2 * bt + 0] = e0 * inv;
            sti[2 * bt + 1] = i1; stw[2 * bt + 1] = e1f * inv;
        }
    }
    __syncthreads();

    if (tid < 8) {
        const int e = tid;
        int cnt = 0;
#pragma unroll
        for (int k = 0; k < 32; k++) cnt += (sti[k] == e) ? 1 : 0;
        int base = atomicAdd(&g_cnt[e], cnt);
        for (int k = 0; k < 32; k++) {
            if (sti[k] == e) {
                const int bt = k >> 1, ch = k & 1;
                const int t = blockIdx.x * 16 + bt;
                const int slot = e * T_DIM + base;
                g_tok[slot] = t;
                g_slot[2 * t + ch] = slot;
                g_wgt[2 * t + ch] = stw[k];
                base++;
            }
        }
    }
}

// ======================= GEMM kernels (fp16 mma + ldmatrix + cp.async) =======================
#define STAGE_BYTES 32768
#define G1_SMEM (1024 + STAGES * STAGE_BYTES)
#define G2_SMEM (1024 + STAGES * STAGE_BYTES)

// ---------------- kernel 2: grouped GEMM1 + SwiGLU -> g_act_h ----------------
// Grid z==0: w2 fp32->fp16 converter plane (1024 blocks, MLP-8 streaming).
// Grid z in 1..8: expert e = z-1 GEMM tiles (unchanged from best config).
__global__ __launch_bounds__(256, 2) void k_gemm1(const float* __restrict__ b1,
                                                  const float4* __restrict__ w2f)
{
    extern __shared__ char smem[];
    const int tid = threadIdx.x;

    if (blockIdx.z == 0) {
        // ---- w2 converter: 1024 blocks x 4096 float4, 16/thread, unroll 8 ----
        const int cidx = blockIdx.y * gridDim.x + blockIdx.x;   // 0..1023
        const long base = (long)cidx * 4096 + tid;
        uint2* dst = (uint2*)g_w2h;
#pragma unroll
        for (int k = 0; k < 16; k += 8) {
            float4 v[8];
#pragma unroll
            for (int j = 0; j < 8; j++) v[j] = w2f[base + (long)(k + j) * 256];
#pragma unroll
            for (int j = 0; j < 8; j++) dst[base + (long)(k + j) * 256] = cvt4(v[j]);
        }
        return;
    }

    const int e  = blockIdx.z - 1;
    const int ne = g_cnt[e];
    const int m0 = blockIdx.y * 128;
    if (m0 >= ne) return;
    const int n0 = blockIdx.x * 64;
    const int lane = tid & 31, wid = tid >> 5;
    const int wm = wid >> 2, wn = wid & 3;
    const uint32_t sb = smem_u32(smem);

    int* stok = (int*)smem;
    if (tid < 128) {
        const int m = m0 + tid;
        stok[tid] = g_tok[e * T_DIM + (m < ne ? m : ne - 1)];
    }
    __syncthreads();

    const __half* w1g = g_w1h + ((size_t)e * 2 * I_DIM + n0) * H_DIM;
    const __half* w1l = w1g + (size_t)I_DIM * H_DIM;

    const int c8  = tid & 7;
    const int r32 = tid >> 3;
    const uint32_t swz = (uint32_t)((c8 ^ (r32 & 7)) << 4);
    const __half* asrc[4];
    const __half* bsrc[4];
    uint32_t adst[4], bdst[4];
#pragma unroll
    for (int i = 0; i < 4; i++) {
        const int row = r32 + i * 32;
        asrc[i] = g_normed_h + (size_t)stok[row] * H_DIM + c8 * 8;
        bsrc[i] = ((row < 64) ? (w1g + (size_t)row * H_DIM)
                              : (w1l + (size_t)(row - 64) * H_DIM)) + c8 * 8;
        adst[i] = sb + 1024u + (uint32_t)row * 128u + swz;
        bdst[i] = adst[i] + 16384u;
    }

#define G1_ISSUE(kt, s) do { \
    const uint32_t so = (uint32_t)(s) * STAGE_BYTES; \
    const int ko = (kt) * 64; \
    _Pragma("unroll") \
    for (int i = 0; i < 4; i++) { \
        cp16(adst[i] + so, asrc[i] + ko); \
        cp16(bdst[i] + so, bsrc[i] + ko); \
    } } while (0)

    const int NK = H_DIM / 64;   // 16
    G1_ISSUE(0, 0); CP_COMMIT();
    G1_ISSUE(1, 1); CP_COMMIT();

    float accg[4][2][4] = {}, accl[4][2][4] = {};

    const int lr  = lane & 7;
    const int rA  = ((lane >> 3) & 1) * 8 + lr;
    const int cA  = (lane >> 4);
    const int rB  = ((lane >> 4) & 1) * 8 + lr;
    const int cB  = ((lane >> 3) & 1);

    for (int c = 0; c < NK; c++) {
        CP_WAIT1();
        __syncthreads();
        if (c + 2 < NK) G1_ISSUE(c + 2, (c + 2) % STAGES);
        CP_COMMIT();

        const uint32_t Asm = sb + 1024u + (uint32_t)(c % STAGES) * STAGE_BYTES;
        const uint32_t Bsm = Asm + 16384u;
#pragma unroll
        for (int ks = 0; ks < 4; ks++) {
            uint32_t a[4][4];
            const uint32_t chA = (uint32_t)(((2 * ks + cA) ^ lr) << 4);
#pragma unroll
            for (int mf = 0; mf < 4; mf++) {
                const int row = wm * 64 + mf * 16 + rA;
                ldsm4(a[mf], Asm + (uint32_t)row * 128u + chA);
            }
            uint32_t bg[4], bl[4];
            const uint32_t chB = (uint32_t)(((2 * ks + cB) ^ lr) << 4);
            ldsm4(bg, Bsm + (uint32_t)(wn * 16 + rB) * 128u + chB);
            ldsm4(bl, Bsm + (uint32_t)(64 + wn * 16 + rB) * 128u + chB);
#pragma unroll
            for (int mf = 0; mf < 4; mf++) {
#pragma unroll
                for (int nf = 0; nf < 2; nf++) {
                    mma_f16(accg[mf][nf], a[mf], bg + 2 * nf);
                    mma_f16(accl[mf][nf], a[mf], bl + 2 * nf);
                }
            }
        }
    }

    const float* bgb = b1 + (size_t)e * 2 * I_DIM + n0;
    const float* blb = bgb + I_DIM;
#pragma unroll
    for (int mf = 0; mf < 4; mf++) {
        const int mb = m0 + wm * 64 + mf * 16 + (lane >> 2);
#pragma unroll
        for (int h = 0; h < 2; h++) {
            const int m = mb + h * 8;
            if (m < ne) {
                __half* orow = g_act_h + ((size_t)e * T_DIM + m) * I_DIM + n0;
#pragma unroll
                for (int nf = 0; nf < 2; nf++) {
                    const int nloc = wn * 16 + nf * 8 + 2 * (lane & 3);
                    const float g0 = accg[mf][nf][2 * h + 0] + bgb[nloc];
                    const float g1 = accg[mf][nf][2 * h + 1] + bgb[nloc + 1];
                    const float l0 = accl[mf][nf][2 * h + 0] + blb[nloc];
                    const float l1 = accl[mf][nf][2 * h + 1] + blb[nloc + 1];
                    __half2 o = __floats2half2_rn(swiglu(g0, l0), swiglu(g1, l1));
                    *(__half2*)(orow + nloc) = o;
                }
            }
        }
    }
#undef G1_ISSUE
}

// ---------------- kernel 3: grouped GEMM2 + bias -> g_out2h (fp16) ----------------
__global__ __launch_bounds__(256, 2) void k_gemm2(const float* __restrict__ b2)
{
    extern __shared__ char smem[];
    const int e  = blockIdx.z;
    const int ne = g_cnt[e];
    const int m0 = blockIdx.y * 128;
    if (m0 >= ne) return;
    const int n0 = blockIdx.x * 128;
    const int tid = threadIdx.x, lane = tid & 31, wid = tid >> 5;
    const int wm = wid >> 2, wn = wid & 3;
    const uint32_t sb = smem_u32(smem);

    const __half* a_base = g_act_h + ((size_t)e * T_DIM + m0) * I_DIM;
    const __half* b_base = g_w2h + ((size_t)e * H_DIM + n0) * I_DIM;

    const int c8  = tid & 7;
    const int r32 = tid >> 3;
    const uint32_t swz = (uint32_t)((c8 ^ (r32 & 7)) << 4);
    const __half* asrc[4];
    const __half* bsrc[4];
    uint32_t adst[4], bdst[4];
#pragma unroll
    for (int i = 0; i < 4; i++) {
        const int row = r32 + i * 32;
        asrc[i] = a_base + (size_t)row * I_DIM + c8 * 8;
        bsrc[i] = b_base + (size_t)row * I_DIM + c8 * 8;
        adst[i] = sb + 1024u + (uint32_t)row * 128u + swz;
        bdst[i] = adst[i] + 16384u;
    }

#define G2_ISSUE(kt, s) do { \
    const uint32_t so = (uint32_t)(s) * STAGE_BYTES; \
    const int ko = (kt) * 64; \
    _Pragma("unroll") \
    for (int i = 0; i < 4; i++) { \
        cp16(adst[i] + so, asrc[i] + ko); \
        cp16(bdst[i] + so, bsrc[i] + ko); \
    } } while (0)

    const int NK = I_DIM / 64;   // 32
    G2_ISSUE(0, 0); CP_COMMIT();
    G2_ISSUE(1, 1); CP_COMMIT();

    float acc[4][4][4] = {};

    const int lr  = lane & 7;
    const int rA  = ((lane >> 3) & 1) * 8 + lr;
    const int cA  = (lane >> 4);
    const int rB  = ((lane >> 4) & 1) * 8 + lr;
    const int cB  = ((lane >> 3) & 1);

    for (int c = 0; c < NK; c++) {
        CP_WAIT1();
        __syncthreads();
        if (c + 2 < NK) G2_ISSUE(c + 2, (c + 2) % STAGES);
        CP_COMMIT();

        const uint32_t Asm = sb + 1024u + (uint32_t)(c % STAGES) * STAGE_BYTES;
        const uint32_t Bsm = Asm + 16384u;
#pragma unroll
        for (int ks = 0; ks < 4; ks++) {
            uint32_t a[4][4];
            const uint32_t chA = (uint32_t)(((2 * ks + cA) ^ lr) << 4);
#pragma unroll
            for (int mf = 0; mf < 4; mf++) {
                const int row = wm * 64 + mf * 16 + rA;
                ldsm4(a[mf], Asm + (uint32_t)row * 128u + chA);
            }
            uint32_t b[2][4];
            const uint32_t chB = (uint32_t)(((2 * ks + cB) ^ lr) << 4);
            ldsm4(b[0], Bsm + (uint32_t)(wn * 32 + rB) * 128u + chB);
            ldsm4(b[1], Bsm + (uint32_t)(wn * 32 + 16 + rB) * 128u + chB);
#pragma unroll
            for (int mf = 0; mf < 4; mf++) {
#pragma unroll
                for (int nf = 0; nf < 4; nf++)
                    mma_f16(acc[mf][nf], a[mf], b[nf >> 1] + 2 * (nf & 1));
            }
        }
    }

    const float* bb = b2 + (size_t)e * H_DIM + n0;
#pragma unroll
    for (int mf = 0; mf < 4; mf++) {
        const int mb = m0 + wm * 64 + mf * 16 + (lane >> 2);
#pragma unroll
        for (int h = 0; h < 2; h++) {
            const int m = mb + h * 8;
            if (m < ne) {
                __half* orow = g_out2h + ((size_t)e * T_DIM + m) * H_DIM + n0;
#pragma unroll
                for (int nf = 0; nf < 4; nf++) {
                    const int nloc = wn * 32 + nf * 8 + 2 * (lane & 3);
                    __half2 o = __floats2half2_rn(acc[mf][nf][2 * h + 0] + bb[nloc],
                                                  acc[mf][nf][2 * h + 1] + bb[nloc + 1]);
                    *(__half2*)(orow + nloc) = o;
                }
            }
        }
    }
#undef G2_ISSUE
}

// ---------------- kernel 4: gather-combine + residual (8 elems / thread) ----------------
__global__ __launch_bounds__(256) void k_combine(
    const float* __restrict__ x, float* __restrict__ out)
{
    const size_t idx = (size_t)blockIdx.x * blockDim.x + threadIdx.x;  // over T*H/8
    if (idx >= (size_t)T_DIM * H_DIM / 8) return;
    const int t  = (int)(idx / (H_DIM / 8));
    const int hc = (int)(idx % (H_DIM / 8)) * 8;

    const int   s0 = g_slot[2 * t + 0], s1 = g_slot[2 * t + 1];
    const float w0 = g_wgt[2 * t + 0],  w1 = g_wgt[2 * t + 1];

    const float4 u0 = *(const float4*)(g_out2h + (size_t)s0 * H_DIM + hc);   // 8 halves
    const float4 u1 = *(const float4*)(g_out2h + (size_t)s1 * H_DIM + hc);
    const __half2* h0 = (const __half2*)&u0;
    const __half2* h1 = (const __half2*)&u1;

    const float* xp = x + (size_t)t * H_DIM + hc;
    float* op = out + (size_t)t * H_DIM + hc;
    const float4 xa = *(const float4*)xp;
    const float4 xb = *(const float4*)(xp + 4);

    float r[8];
#pragma unroll
    for (int q = 0; q < 4; q++) {
        const float2 f0 = __half22float2(h0[q]);
        const float2 f1 = __half22float2(h1[q]);
        r[2 * q + 0] = w0 * f0.x + w1 * f1.x;
        r[2 * q + 1] = w0 * f0.y + w1 * f1.y;
    }
    float4 oa = { xa.x + r[0], xa.y + r[1], xa.z + r[2], xa.w + r[3] };
    float4 ob = { xb.x + r[4], xb.y + r[5], xb.z + r[6], xb.w + r[7] };
    *(float4*)op = oa;
    *(float4*)(op + 4) = ob;
}

// ---------------- launch ----------------
extern "C" void kernel_launch(void* const* d_in, const int* in_sizes, int n_in,
                              void* d_out, int out_size)
{
    const float* x     = (const float*)d_in[0];
    const float* scale = (const float*)d_in[1];
    const float* gk    = (const float*)d_in[2];
    const float* gb    = (const float*)d_in[3];
    const float* w1    = (const float*)d_in[4];
    const float* b1    = (const float*)d_in[5];
    const float* w2    = (const float*)d_in[6];
    const float* b2    = (const float*)d_in[7];
    float* out = (float*)d_out;

    cudaFuncSetAttribute(k_gemm1, cudaFuncAttributeMaxDynamicSharedMemorySize, G1_SMEM);
    cudaFuncSetAttribute(k_gemm2, cudaFuncAttributeMaxDynamicSharedMemorySize, G2_SMEM);

    // w1 conversion (+ counter zero in block 0)
    {
        __half* w1h_p; cudaGetSymbolAddress((void**)&w1h_p, g_w1h);
        const int n4_1 = E_DIM * 2 * I_DIM * H_DIM / 4;   // 8.39M
        k_cvt<<<n4_1 / 256, 256>>>((const float4*)w1, (uint2*)w1h_p, n4_1);
    }

    k_rms_gate<<<T_DIM / 16, 256>>>(x, scale, gk, gb);

    // z==0: w2 converter plane; z in 1..8: experts
    dim3 g1(I_DIM / 64, T_DIM / 128, E_DIM + 1);   // 32 x 32 x 9
    k_gemm1<<<g1, 256, G1_SMEM>>>(b1, (const float4*)w2);

    dim3 g2(H_DIM / 128, T_DIM / 128, E_DIM);      // 8 x 32 x 8
    k_gemm2<<<g2, 256, G2_SMEM>>>(b2);

    k_combine<<<(T_DIM * H_DIM / 8 + 255) / 256, 256>>>(x, out);
}

// round 16
// speedup vs baseline: 1.1217x; 1.0307x over previous
#include <cuda_runtime.h>
#include <cuda_fp16.h>
#include <math.h>
#include <stdint.h>

#define T_DIM 4096
#define H_DIM 1024
#define E_DIM 8
#define I_DIM 2048
#define STAGES 3

// ---------------- scratch (static device globals) ----------------
__device__ __half g_w1h[(size_t)E_DIM * 2 * I_DIM * H_DIM];   // 67 MB
__device__ __half g_w2h[(size_t)E_DIM * H_DIM * I_DIM];       // 33.5 MB
__device__ __half g_normed_h[(size_t)T_DIM * H_DIM];          // 8 MB
__device__ __half g_act_h[(size_t)E_DIM * T_DIM * I_DIM];     // 134 MB
__device__ __half g_out2h[(size_t)E_DIM * T_DIM * H_DIM];     // 67 MB
__device__ int    g_cnt[E_DIM];
__device__ int    g_tok[E_DIM * T_DIM];
__device__ int    g_slot[T_DIM * 2];
__device__ float  g_wgt[T_DIM * 2];

// ---------------- PTX helpers ----------------
__device__ __forceinline__ uint32_t smem_u32(const void* p) {
    uint32_t a;
    asm("{ .reg .u64 t; cvta.to.shared.u64 t, %1; cvt.u32.u64 %0, t; }" : "=r"(a) : "l"(p));
    return a;
}
__device__ __forceinline__ void cp16(uint32_t dst, const void* src) {
    asm volatile("cp.async.cg.shared.global [%0], [%1], 16;" :: "r"(dst), "l"(src));
}
#define CP_COMMIT() asm volatile("cp.async.commit_group;" ::: "memory")
#define CP_WAIT1()  asm volatile("cp.async.wait_group 1;" ::: "memory")
__device__ __forceinline__ void ldsm4(uint32_t* r, uint32_t addr) {
    asm volatile("ldmatrix.sync.aligned.m8n8.x4.shared.b16 {%0,%1,%2,%3}, [%4];"
        : "=r"(r[0]), "=r"(r[1]), "=r"(r[2]), "=r"(r[3]) : "r"(addr));
}
__device__ __forceinline__ void mma_f16(float* c, const uint32_t* a, const uint32_t* b) {
    asm("mma.sync.aligned.m16n8k16.row.col.f32.f16.f16.f32 "
        "{%0,%1,%2,%3},{%4,%5,%6,%7},{%8,%9},{%0,%1,%2,%3};"
        : "+f"(c[0]), "+f"(c[1]), "+f"(c[2]), "+f"(c[3])
        : "r"(a[0]), "r"(a[1]), "r"(a[2]), "r"(a[3]), "r"(b[0]), "r"(b[1]));
}
__device__ __forceinline__ uint2 cvt4(float4 v) {
    __half2 a = __floats2half2_rn(v.x, v.y);
    __half2 b = __floats2half2_rn(v.z, v.w);
    uint2 u;
    u.x = *(const uint32_t*)&a;
    u.y = *(const uint32_t*)&b;
    return u;
}
__device__ __forceinline__ float swiglu(float gv, float lv) {
    gv = fminf(gv, 7.f);
    lv = fminf(fmaxf(lv, -7.f), 7.f);
    const float sw = gv / (1.f + expf(-1.702f * gv));
    return sw * (lv + 1.f);
}

// ---------------- kernel 1: RMSNorm+gate+routing (blocks 0..255)
//                            + w1 fp32->fp16 convert (blocks 256..2303, unroll-8 MLP) ----------------
#define RMS_BLK 256
#define W1_CVT_BLK 2048
__global__ __launch_bounds__(256) void k_rms_cvt(
    const float* __restrict__ x, const float* __restrict__ scale,
    const float* __restrict__ gk, const float* __restrict__ gb,
    const float4* __restrict__ w1f)
{
    const int tid = threadIdx.x, lane = tid & 31, wid = tid >> 5;

    if (blockIdx.x >= RMS_BLK) {
        // ---- w1 converter: 2048 blocks x 4096 float4, 16/thread, unroll 8 ----
        const int cidx = blockIdx.x - RMS_BLK;           // 0..2047
        const long base = (long)cidx * 4096 + tid;
        uint2* dst = (uint2*)g_w1h;
#pragma unroll
        for (int k = 0; k < 16; k += 8) {
            float4 v[8];
#pragma unroll
            for (int j = 0; j < 8; j++) v[j] = w1f[base + (long)(k + j) * 256];
#pragma unroll
            for (int j = 0; j < 8; j++) dst[base + (long)(k + j) * 256] = cvt4(v[j]);
        }
        return;
    }

    // ---- RMSNorm + gate + top-2 + routing (16 tokens / block) ----
    __shared__ float4 sgk4[2048];   // 32 KB swizzled gk
    __shared__ int    sti[32];
    __shared__ float  stw[32];

    const float4* gk4 = (const float4*)gk;
#pragma unroll
    for (int q = tid; q < 2048; q += 256)
        sgk4[q ^ ((q >> 3) & 1)] = gk4[q];
    __syncthreads();

#pragma unroll
    for (int it = 0; it < 2; it++) {
        const int t = blockIdx.x * 16 + wid * 2 + it;
        const float* xrow = x + (size_t)t * H_DIM;

        float xr[32];
        float ss = 0.f;
#pragma unroll
        for (int j = 0; j < 32; j++) {
            xr[j] = xrow[j * 32 + lane];
            ss += xr[j] * xr[j];
        }
#pragma unroll
        for (int o = 16; o > 0; o >>= 1) ss += __shfl_xor_sync(0xffffffffu, ss, o);
        const float rinv = rsqrtf(ss * (1.0f / H_DIM) + 1e-5f);

        __half* nrow = g_normed_h + (size_t)t * H_DIM;
#pragma unroll
        for (int j = 0; j < 32; j++) {
            const int h = j * 32 + lane;
            xr[j] = xr[j] * rinv * __ldg(scale + h);
            nrow[h] = __float2half_rn(xr[j]);
        }

        float acc[8];
#pragma unroll
        for (int e2 = 0; e2 < 8; e2++) acc[e2] = 0.f;
#pragma unroll
        for (int j = 0; j < 32; j++) {
            const int h = j * 32 + lane;
            const int b = (h >> 2) & 1;
            const float4 g0 = sgk4[(2 * h) ^ b];
            const float4 g1 = sgk4[(2 * h + 1) ^ b];
            const float nv = xr[j];
            acc[0] += nv * g0.x; acc[1] += nv * g0.y;
            acc[2] += nv * g0.z; acc[3] += nv * g0.w;
            acc[4] += nv * g1.x; acc[5] += nv * g1.y;
            acc[6] += nv * g1.z; acc[7] += nv * g1.w;
        }
#pragma unroll
        for (int e2 = 0; e2 < 8; e2++) {
#pragma unroll
            for (int o = 16; o > 0; o >>= 1)
                acc[e2] += __shfl_xor_sync(0xffffffffu, acc[e2], o);
        }

        if (lane == 0) {
            float lg[8];
#pragma unroll
            for (int e2 = 0; e2 < 8; e2++) lg[e2] = acc[e2] + __ldg(gb + e2);
            int i0 = 0; float l0 = lg[0];
#pragma unroll
            for (int e2 = 1; e2 < 8; e2++) { if (lg[e2] > l0) { l0 = lg[e2]; i0 = e2; } }
            int i1 = -1; float l1 = -3.4e38f;
#pragma unroll
            for (int e2 = 0; e2 < 8; e2++) {
                if (e2 != i0 && lg[e2] > l1) { l1 = lg[e2]; i1 = e2; }
            }
            const float m  = fmaxf(l0, l1);
            const float e0 = expf(l0 - m), e1f = expf(l1 - m);
            const float inv = 1.0f / (e0 + e1f);
            const int bt = wid * 2 + it;
            sti[2 * bt + 0] = i0; stw[2 * bt + 0] = e0 * inv;
            sti[2 * bt + 1] = i1; stw[2 * bt + 1] = e1f * inv;
        }
    }
    __syncthreads();

    if (tid < 8) {
        const int e = tid;
        int cnt = 0;
#pragma unroll
        for (int k = 0; k < 32; k++) cnt += (sti[k] == e) ? 1 : 0;
        int base = atomicAdd(&g_cnt[e], cnt);
        for (int k = 0; k < 32; k++) {
            if (sti[k] == e) {
                const int bt = k >> 1, ch = k & 1;
                const int t = blockIdx.x * 16 + bt;
                const int slot = e * T_DIM + base;
                g_tok[slot] = t;
                g_slot[2 * t + ch] = slot;
                g_wgt[2 * t + ch] = stw[k];
                base++;
            }
        }
    }
}

// ======================= GEMM kernels (fp16 mma + ldmatrix + cp.async) =======================
#define STAGE_BYTES 32768
#define G1_SMEM (1024 + STAGES * STAGE_BYTES)
#define G2_SMEM (1024 + STAGES * STAGE_BYTES)

// ---------------- kernel 2: grouped GEMM1 + SwiGLU -> g_act_h ----------------
// Grid z==0: w2 fp32->fp16 converter plane. z in 1..8: expert e = z-1.
__global__ __launch_bounds__(256, 2) void k_gemm1(const float* __restrict__ b1,
                                                  const float4* __restrict__ w2f)
{
    extern __shared__ char smem[];
    const int tid = threadIdx.x;

    if (blockIdx.z == 0) {
        const int cidx = blockIdx.y * gridDim.x + blockIdx.x;   // 0..1023
        const long base = (long)cidx * 4096 + tid;
        uint2* dst = (uint2*)g_w2h;
#pragma unroll
        for (int k = 0; k < 16; k += 8) {
            float4 v[8];
#pragma unroll
            for (int j = 0; j < 8; j++) v[j] = w2f[base + (long)(k + j) * 256];
#pragma unroll
            for (int j = 0; j < 8; j++) dst[base + (long)(k + j) * 256] = cvt4(v[j]);
        }
        return;
    }

    const int e  = blockIdx.z - 1;
    const int ne = g_cnt[e];
    const int m0 = blockIdx.y * 128;
    if (m0 >= ne) return;
    const int n0 = blockIdx.x * 64;
    const int lane = tid & 31, wid = tid >> 5;
    const int wm = wid >> 2, wn = wid & 3;
    const uint32_t sb = smem_u32(smem);

    int* stok = (int*)smem;
    if (tid < 128) {
        const int m = m0 + tid;
        stok[tid] = g_tok[e * T_DIM + (m < ne ? m : ne - 1)];
    }
    __syncthreads();

    const __half* w1g = g_w1h + ((size_t)e * 2 * I_DIM + n0) * H_DIM;
    const __half* w1l = w1g + (size_t)I_DIM * H_DIM;

    const int c8  = tid & 7;
    const int r32 = tid >> 3;
    const uint32_t swz = (uint32_t)((c8 ^ (r32 & 7)) << 4);
    const __half* asrc[4];
    const __half* bsrc[4];
    uint32_t adst[4], bdst[4];
#pragma unroll
    for (int i = 0; i < 4; i++) {
        const int row = r32 + i * 32;
        asrc[i] = g_normed_h + (size_t)stok[row] * H_DIM + c8 * 8;
        bsrc[i] = ((row < 64) ? (w1g + (size_t)row * H_DIM)
                              : (w1l + (size_t)(row - 64) * H_DIM)) + c8 * 8;
        adst[i] = sb + 1024u + (uint32_t)row * 128u + swz;
        bdst[i] = adst[i] + 16384u;
    }

#define G1_ISSUE(kt, s) do { \
    const uint32_t so = (uint32_t)(s) * STAGE_BYTES; \
    const int ko = (kt) * 64; \
    _Pragma("unroll") \
    for (int i = 0; i < 4; i++) { \
        cp16(adst[i] + so, asrc[i] + ko); \
        cp16(bdst[i] + so, bsrc[i] + ko); \
    } } while (0)

    const int NK = H_DIM / 64;   // 16
    G1_ISSUE(0, 0); CP_COMMIT();
    G1_ISSUE(1, 1); CP_COMMIT();

    float accg[4][2][4] = {}, accl[4][2][4] = {};

    const int lr  = lane & 7;
    const int rA  = ((lane >> 3) & 1) * 8 + lr;
    const int cA  = (lane >> 4);
    const int rB  = ((lane >> 4) & 1) * 8 + lr;
    const int cB  = ((lane >> 3) & 1);

    for (int c = 0; c < NK; c++) {
        CP_WAIT1();
        __syncthreads();
        if (c + 2 < NK) G1_ISSUE(c + 2, (c + 2) % STAGES);
        CP_COMMIT();

        const uint32_t Asm = sb + 1024u + (uint32_t)(c % STAGES) * STAGE_BYTES;
        const uint32_t Bsm = Asm + 16384u;
#pragma unroll
        for (int ks = 0; ks < 4; ks++) {
            uint32_t a[4][4];
            const uint32_t chA = (uint32_t)(((2 * ks + cA) ^ lr) << 4);
#pragma unroll
            for (int mf = 0; mf < 4; mf++) {
                const int row = wm * 64 + mf * 16 + rA;
                ldsm4(a[mf], Asm + (uint32_t)row * 128u + chA);
            }
            uint32_t bg[4], bl[4];
            const uint32_t chB = (uint32_t)(((2 * ks + cB) ^ lr) << 4);
            ldsm4(bg, Bsm + (uint32_t)(wn * 16 + rB) * 128u + chB);
            ldsm4(bl, Bsm + (uint32_t)(64 + wn * 16 + rB) * 128u + chB);
#pragma unroll
            for (int mf = 0; mf < 4; mf++) {
#pragma unroll
                for (int nf = 0; nf < 2; nf++) {
                    mma_f16(accg[mf][nf], a[mf], bg + 2 * nf);
                    mma_f16(accl[mf][nf], a[mf], bl + 2 * nf);
                }
            }
        }
    }

    const float* bgb = b1 + (size_t)e * 2 * I_DIM + n0;
    const float* blb = bgb + I_DIM;
#pragma unroll
    for (int mf = 0; mf < 4; mf++) {
        const int mb = m0 + wm * 64 + mf * 16 + (lane >> 2);
#pragma unroll
        for (int h = 0; h < 2; h++) {
            const int m = mb + h * 8;
            if (m < ne) {
                __half* orow = g_act_h + ((size_t)e * T_DIM + m) * I_DIM + n0;
#pragma unroll
                for (int nf = 0; nf < 2; nf++) {
                    const int nloc = wn * 16 + nf * 8 + 2 * (lane & 3);
                    const float g0 = accg[mf][nf][2 * h + 0] + bgb[nloc];
                    const float g1 = accg[mf][nf][2 * h + 1] + bgb[nloc + 1];
                    const float l0 = accl[mf][nf][2 * h + 0] + blb[nloc];
                    const float l1 = accl[mf][nf][2 * h + 1] + blb[nloc + 1];
                    __half2 o = __floats2half2_rn(swiglu(g0, l0), swiglu(g1, l1));
                    *(__half2*)(orow + nloc) = o;
                }
            }
        }
    }
#undef G1_ISSUE
}

// ---------------- kernel 3: grouped GEMM2 + bias -> g_out2h (fp16) ----------------
__global__ __launch_bounds__(256, 2) void k_gemm2(const float* __restrict__ b2)
{
    extern __shared__ char smem[];
    const int e  = blockIdx.z;
    const int ne = g_cnt[e];
    const int m0 = blockIdx.y * 128;
    if (m0 >= ne) return;
    const int n0 = blockIdx.x * 128;
    const int tid = threadIdx.x, lane = tid & 31, wid = tid >> 5;
    const int wm = wid >> 2, wn = wid & 3;
    const uint32_t sb = smem_u32(smem);

    const __half* a_base = g_act_h + ((size_t)e * T_DIM + m0) * I_DIM;
    const __half* b_base = g_w2h + ((size_t)e * H_DIM + n0) * I_DIM;

    const int c8  = tid & 7;
    const int r32 = tid >> 3;
    const uint32_t swz = (uint32_t)((c8 ^ (r32 & 7)) << 4);
    const __half* asrc[4];
    const __half* bsrc[4];
    uint32_t adst[4], bdst[4];
#pragma unroll
    for (int i = 0; i < 4; i++) {
        const int row = r32 + i * 32;
        asrc[i] = a_base + (size_t)row * I_DIM + c8 * 8;
        bsrc[i] = b_base + (size_t)row * I_DIM + c8 * 8;
        adst[i] = sb + 1024u + (uint32_t)row * 128u + swz;
        bdst[i] = adst[i] + 16384u;
    }

#define G2_ISSUE(kt, s) do { \
    const uint32_t so = (uint32_t)(s) * STAGE_BYTES; \
    const int ko = (kt) * 64; \
    _Pragma("unroll") \
    for (int i = 0; i < 4; i++) { \
        cp16(adst[i] + so, asrc[i] + ko); \
        cp16(bdst[i] + so, bsrc[i] + ko); \
    } } while (0)

    const int NK = I_DIM / 64;   // 32
    G2_ISSUE(0, 0); CP_COMMIT();
    G2_ISSUE(1, 1); CP_COMMIT();

    float acc[4][4][4] = {};

    const int lr  = lane & 7;
    const int rA  = ((lane >> 3) & 1) * 8 + lr;
    const int cA  = (lane >> 4);
    const int rB  = ((lane >> 4) & 1) * 8 + lr;
    const int cB  = ((lane >> 3) & 1);

    for (int c = 0; c < NK; c++) {
        CP_WAIT1();
        __syncthreads();
        if (c + 2 < NK) G2_ISSUE(c + 2, (c + 2) % STAGES);
        CP_COMMIT();

        const uint32_t Asm = sb + 1024u + (uint32_t)(c % STAGES) * STAGE_BYTES;
        const uint32_t Bsm = Asm + 16384u;
#pragma unroll
        for (int ks = 0; ks < 4; ks++) {
            uint32_t a[4][4];
            const uint32_t chA = (uint32_t)(((2 * ks + cA) ^ lr) << 4);
#pragma unroll
            for (int mf = 0; mf < 4; mf++) {
                const int row = wm * 64 + mf * 16 + rA;
                ldsm4(a[mf], Asm + (uint32_t)row * 128u + chA);
            }
            uint32_t b[2][4];
            const uint32_t chB = (uint32_t)(((2 * ks + cB) ^ lr) << 4);
            ldsm4(b[0], Bsm + (uint32_t)(wn * 32 + rB) * 128u + chB);
            ldsm4(b[1], Bsm + (uint32_t)(wn * 32 + 16 + rB) * 128u + chB);
#pragma unroll
            for (int mf = 0; mf < 4; mf++) {
#pragma unroll
                for (int nf = 0; nf < 4; nf++)
                    mma_f16(acc[mf][nf], a[mf], b[nf >> 1] + 2 * (nf & 1));
            }
        }
    }

    const float* bb = b2 + (size_t)e * H_DIM + n0;
#pragma unroll
    for (int mf = 0; mf < 4; mf++) {
        const int mb = m0 + wm * 64 + mf * 16 + (lane >> 2);
#pragma unroll
        for (int h = 0; h < 2; h++) {
            const int m = mb + h * 8;
            if (m < ne) {
                __half* orow = g_out2h + ((size_t)e * T_DIM + m) * H_DIM + n0;
#pragma unroll
                for (int nf = 0; nf < 4; nf++) {
                    const int nloc = wn * 32 + nf * 8 + 2 * (lane & 3);
                    __half2 o = __floats2half2_rn(acc[mf][nf][2 * h + 0] + bb[nloc],
                                                  acc[mf][nf][2 * h + 1] + bb[nloc + 1]);
                    *(__half2*)(orow + nloc) = o;
                }
            }
        }
    }
#undef G2_ISSUE
}

// ---------------- kernel 4: gather-combine + residual (8 elems / thread) ----------------
__global__ __launch_bounds__(256) void k_combine(
    const float* __restrict__ x, float* __restrict__ out)
{
    const size_t idx = (size_t)blockIdx.x * blockDim.x + threadIdx.x;  // over T*H/8
    if (idx >= (size_t)T_DIM * H_DIM / 8) return;
    const int t  = (int)(idx / (H_DIM / 8));
    const int hc = (int)(idx % (H_DIM / 8)) * 8;

    const int   s0 = g_slot[2 * t + 0], s1 = g_slot[2 * t + 1];
    const float w0 = g_wgt[2 * t + 0],  w1 = g_wgt[2 * t + 1];

    const float4 u0 = *(const float4*)(g_out2h + (size_t)s0 * H_DIM + hc);   // 8 halves
    const float4 u1 = *(const float4*)(g_out2h + (size_t)s1 * H_DIM + hc);
    const __half2* h0 = (const __half2*)&u0;
    const __half2* h1 = (const __half2*)&u1;

    const float* xp = x + (size_t)t * H_DIM + hc;
    float* op = out + (size_t)t * H_DIM + hc;
    const float4 xa = *(const float4*)xp;
    const float4 xb = *(const float4*)(xp + 4);

    float r[8];
#pragma unroll
    for (int q = 0; q < 4; q++) {
        const float2 f0 = __half22float2(h0[q]);
        const float2 f1 = __half22float2(h1[q]);
        r[2 * q + 0] = w0 * f0.x + w1 * f1.x;
        r[2 * q + 1] = w0 * f0.y + w1 * f1.y;
    }
    float4 oa = { xa.x + r[0], xa.y + r[1], xa.z + r[2], xa.w + r[3] };
    float4 ob = { xb.x + r[4], xb.y + r[5], xb.z + r[6], xb.w + r[7] };
    *(float4*)op = oa;
    *(float4*)(op + 4) = ob;
}

// ---------------- launch ----------------
extern "C" void kernel_launch(void* const* d_in, const int* in_sizes, int n_in,
                              void* d_out, int out_size)
{
    const float* x     = (const float*)d_in[0];
    const float* scale = (const float*)d_in[1];
    const float* gk    = (const float*)d_in[2];
    const float* gb    = (const float*)d_in[3];
    const float* w1    = (const float*)d_in[4];
    const float* b1    = (const float*)d_in[5];
    const float* w2    = (const float*)d_in[6];
    const float* b2    = (const float*)d_in[7];
    float* out = (float*)d_out;

    cudaFuncSetAttribute(k_gemm1, cudaFuncAttributeMaxDynamicSharedMemorySize, G1_SMEM);
    cudaFuncSetAttribute(k_gemm2, cudaFuncAttributeMaxDynamicSharedMemorySize, G2_SMEM);

    // counter zeroing via memset node (graph-capturable, ordered before k_rms_cvt)
    {
        int* cnt_p; cudaGetSymbolAddress((void**)&cnt_p, g_cnt);
        cudaMemsetAsync(cnt_p, 0, E_DIM * sizeof(int));
    }

    // rms/gating (blocks 0..255) + w1 conversion (blocks 256..2303)
    k_rms_cvt<<<RMS_BLK + W1_CVT_BLK, 256>>>(x, scale, gk, gb, (const float4*)w1);

    // z==0: w2 converter plane; z in 1..8: experts
    dim3 g1(I_DIM / 64, T_DIM / 128, E_DIM + 1);   // 32 x 32 x 9
    k_gemm1<<<g1, 256, G1_SMEM>>>(b1, (const float4*)w2);

    dim3 g2(H_DIM / 128, T_DIM / 128, E_DIM);      // 8 x 32 x 8
    k_gemm2<<<g2, 256, G2_SMEM>>>(b2);

    k_combine<<<(T_DIM * H_DIM / 8 + 255) / 256, 256>>>(x, out);
}